// round 11
// baseline (speedup 1.0000x reference)
#include <cuda_runtime.h>
#include <cuda_fp16.h>
#include <cstdint>

// ---------------- problem constants ----------------
#define K_DIM   256
#define N_DIM   256
#define M_CTA   64
#define N_CTA   128
#define THREADS 256           // 8 warps: 2(M) x 2(N) x 2(K-half), warp tile 32x64

// smem layout (bytes) -- unpadded XOR-swizzled fp16 tiles (512 B rows)
#define OFF_SCALE 0                           // 128 f32
#define OFF_BIAS  512                         // 128 f32
#define OFF_A     1024
#define A_REGION  33792                       // A data 32768; staging 64x132 f32 = 33792
#define OFF_B     (OFF_A + A_REGION)          // 34816
#define B_BYTES   (128 * 512)                 // 65536
#define SMEM_TOTAL (OFF_B + B_BYTES)          // 100352 -> 2 CTAs/SM
#define LDE 132                               // staging stride (floats)

__device__ __forceinline__ uint32_t smem_u32(const void* p) {
    uint32_t a;
    asm("{ .reg .u64 t; cvta.to.shared.u64 t, %1; cvt.u32.u64 %0, t; }"
        : "=r"(a) : "l"(p));
    return a;
}
__device__ __forceinline__ void cp16(uint32_t dst, const void* src) {
    asm volatile("cp.async.cg.shared.global [%0], [%1], 16;" :: "r"(dst), "l"(src) : "memory");
}
#define CP_COMMIT() asm volatile("cp.async.commit_group;" ::: "memory")
#define CP_WAIT0()  asm volatile("cp.async.wait_group 0;" ::: "memory")

__device__ __forceinline__ void ldsm4(uint32_t& r0, uint32_t& r1, uint32_t& r2, uint32_t& r3,
                                      uint32_t addr) {
    asm volatile("ldmatrix.sync.aligned.m8n8.x4.shared.b16 {%0,%1,%2,%3}, [%4];"
                 : "=r"(r0), "=r"(r1), "=r"(r2), "=r"(r3) : "r"(addr));
}
__device__ __forceinline__ void mma16816(float* c, const uint32_t* a, uint32_t b0, uint32_t b1) {
    asm volatile(
        "mma.sync.aligned.m16n8k16.row.col.f32.f16.f16.f32 "
        "{%0,%1,%2,%3}, {%4,%5,%6,%7}, {%8,%9}, {%0,%1,%2,%3};"
        : "+f"(c[0]), "+f"(c[1]), "+f"(c[2]), "+f"(c[3])
        : "r"(a[0]), "r"(a[1]), "r"(a[2]), "r"(a[3]), "r"(b0), "r"(b1));
}

// Binarized weight sign(W) as fp16 (+-1 exact), prepared per launch.
__device__ __align__(16) __half g_bsign[N_DIM * K_DIM];

__global__ void prep_bsign(const float* __restrict__ W) {
    int i = blockIdx.x * blockDim.x + threadIdx.x;
    if (i < N_DIM * K_DIM) {
        float w = W[i];
        g_bsign[i] = __float2half((w > 0.f) ? 1.f : ((w < 0.f) ? -1.f : 0.f));
    }
}

__global__ __launch_bounds__(THREADS, 2)
void binlin_gemm(const float* __restrict__ x,
                 const float* __restrict__ scale,
                 const float* __restrict__ bias,
                 float* __restrict__ out) {
    extern __shared__ char smem[];
    float* sScale = (float*)(smem + OFF_SCALE);
    float* sBias  = (float*)(smem + OFF_BIAS);
    __half* sA    = (__half*)(smem + OFF_A);
    float* stage  = (float*)(smem + OFF_A);      // overlays A after mainloop
    const uint32_t sAu = smem_u32(smem + OFF_A);
    const uint32_t sBu = smem_u32(smem + OFF_B);

    const int tid  = threadIdx.x;
    const int wid  = tid >> 5;
    const int lane = tid & 31;
    const int wm   = wid & 1;         // 0..1 (M, 32 rows)
    const int wn   = (wid >> 1) & 1;  // 0..1 (N, 64 cols)
    const int wk   = wid >> 2;        // 0..1 (K half: k-steps wk*8 .. wk*8+7)
    const int g    = lane >> 2;       // 0..7
    const int t    = lane & 3;        // 0..3

    const int mblk = blockIdx.x >> 1;
    const int nblk = blockIdx.x & 1;
    const int m_base = mblk * M_CTA;
    const int n_base = nblk * N_CTA;

    // ---- scale/bias for this N block ----
    if (tid < 128) {
        sScale[tid] = scale[n_base + tid];
        sBias[tid]  = bias[n_base + tid];
    }

    // ---- B tile via cp.async: 4096 x 16B items, 16/thread; swizzled ----
    {
        const __half* bsrc = g_bsign + (size_t)n_base * K_DIM;
        #pragma unroll
        for (int i = 0; i < 16; i++) {
            int c = tid + THREADS * i;          // 0..4095
            int r = c >> 5;
            int q = c & 31;
            cp16(sBu + r * 512 + 16 * (q ^ (r & 7)), bsrc + r * K_DIM + q * 8);
        }
    }
    CP_COMMIT();

    // ---- A tile: LDG fp32 -> cvt -> STS.128 fp16, swizzled. 2048 items, 8/thread ----
    const float* xbase = x + (size_t)m_base * K_DIM;
    #pragma unroll
    for (int i = 0; i < 8; i++) {
        int c  = tid + THREADS * i;             // 0..2047
        int r  = c >> 5;                        // row 0..63
        int cq = c & 31;                        // 16B dst chunk in row
        const float* src = xbase + (size_t)r * K_DIM + cq * 8;
        float4 v0 = *(const float4*)(src);
        float4 v1 = *(const float4*)(src + 4);
        __half2 h0 = __floats2half2_rn(v0.x, v0.y);
        __half2 h1 = __floats2half2_rn(v0.z, v0.w);
        __half2 h2 = __floats2half2_rn(v1.x, v1.y);
        __half2 h3 = __floats2half2_rn(v1.z, v1.w);
        uint4 u;
        u.x = *(uint32_t*)&h0; u.y = *(uint32_t*)&h1;
        u.z = *(uint32_t*)&h2; u.w = *(uint32_t*)&h3;
        *(uint4*)((char*)sA + r * 512 + 16 * (cq ^ (r & 7))) = u;
    }

    CP_WAIT0();
    __syncthreads();

    // ---- fragment addressing (swizzled 512 B rows) ----
    const int arow = wm * 32 + (lane & 15);
    const int brow = wn * 64 + (lane & 15);
    const int kq   = lane >> 4;                 // 0/1

    float acc[2][8][4];
    #pragma unroll
    for (int i = 0; i < 2; i++)
        #pragma unroll
        for (int j = 0; j < 8; j++)
            #pragma unroll
            for (int e = 0; e < 4; e++)
                acc[i][j][e] = 0.f;

    uint32_t afr[2][2][4];     // [buf][mtile][4]  (dbl-buffer across k-steps)
    uint32_t bfr[2][4];        // [group buf][4]   (dbl-buffer across n16 groups)

    const int ks0 = wk * 8;

    auto loadA = [&](int bb, int ks) {
        const int q = 2 * ks + kq;
        #pragma unroll
        for (int i = 0; i < 2; i++) {
            const int r = arow + i * 16;
            ldsm4(afr[bb][i][0], afr[bb][i][1], afr[bb][i][2], afr[bb][i][3],
                  sAu + r * 512 + 16 * (q ^ (r & 7)));
        }
    };
    auto loadBg = [&](int bb, int ks, int p) {
        const int q = 2 * ks + kq;
        const int r = brow + p * 16;
        ldsm4(bfr[bb][0], bfr[bb][1], bfr[bb][2], bfr[bb][3],
              sBu + r * 512 + 16 * (q ^ (r & 7)));
    };

    loadA(0, ks0);
    loadBg(0, ks0, 0);

    // ---- mainloop: 8 k-steps, B group-pipelined (4 MMAs cover each LDSM) ----
    #pragma unroll
    for (int s = 0; s < 8; s++) {
        const int cur = s & 1;
        const int ks  = ks0 + s;
        if (s < 7) loadA(cur ^ 1, ks + 1);
        #pragma unroll
        for (int p = 0; p < 4; p++) {
            const int pb = p & 1;
            if (p < 3)      loadBg(pb ^ 1, ks, p + 1);
            else if (s < 7) loadBg(pb ^ 1, ks + 1, 0);
            #pragma unroll
            for (int i = 0; i < 2; i++)
                #pragma unroll
                for (int h = 0; h < 2; h++)
                    mma16816(acc[i][p * 2 + h], afr[cur][i], bfr[pb][h], bfr[pb][h + 2]);
        }
    }

    // ---- cross-warp k-reduce through smem staging (overlays A) ----
    __syncthreads();                 // all mainloop A/B reads complete
    if (wk == 1) {
        #pragma unroll
        for (int i = 0; i < 2; i++) {
            const int r0 = wm * 32 + i * 16 + g;
            #pragma unroll
            for (int j = 0; j < 8; j++) {
                const int col = wn * 64 + j * 8 + 2 * t;
                *(float2*)(stage + r0 * LDE + col)       = make_float2(acc[i][j][0], acc[i][j][1]);
                *(float2*)(stage + (r0 + 8) * LDE + col) = make_float2(acc[i][j][2], acc[i][j][3]);
            }
        }
    }
    __syncthreads();

    // ---- wk==0 warps: combine halves, scale/bias, STG ----
    if (wk == 0) {
        #pragma unroll
        for (int i = 0; i < 2; i++) {
            const int rl = wm * 32 + i * 16 + g;
            const int r0 = m_base + rl;
            float* dst0 = out + (size_t)r0 * N_DIM + n_base + wn * 64;
            float* dst1 = dst0 + 8 * N_DIM;
            #pragma unroll
            for (int j = 0; j < 8; j++) {
                const int col = wn * 64 + j * 8 + 2 * t;
                const float2 s0 = *(const float2*)(stage + rl * LDE + col);
                const float2 s1 = *(const float2*)(stage + (rl + 8) * LDE + col);
                const float2 sc = *(const float2*)(sScale + col);
                const float2 bi = *(const float2*)(sBias + col);
                float2 v0, v1;
                v0.x = (acc[i][j][0] + s0.x) * sc.x + bi.x;
                v0.y = (acc[i][j][1] + s0.y) * sc.y + bi.y;
                v1.x = (acc[i][j][2] + s1.x) * sc.x + bi.x;
                v1.y = (acc[i][j][3] + s1.y) * sc.y + bi.y;
                *(float2*)(dst0 + col - wn * 64) = v0;
                *(float2*)(dst1 + col - wn * 64) = v1;
            }
        }
    }
}

extern "C" void kernel_launch(void* const* d_in, const int* in_sizes, int n_in,
                              void* d_out, int out_size) {
    const float* x     = (const float*)d_in[0];
    const float* W     = (const float*)d_in[1];
    const float* scale = (const float*)d_in[2];
    const float* bias  = (const float*)d_in[3];
    float* out = (float*)d_out;

    const int M = in_sizes[0] / K_DIM;              // 131072
    const int grid = (M / M_CTA) * 2;               // 4096

    prep_bsign<<<(N_DIM * K_DIM + 255) / 256, 256>>>(W);

    cudaFuncSetAttribute(binlin_gemm, cudaFuncAttributeMaxDynamicSharedMemorySize, SMEM_TOTAL);
    binlin_gemm<<<grid, THREADS, SMEM_TOTAL>>>(x, scale, bias, out);
}

// round 12
// speedup vs baseline: 1.2682x; 1.2682x over previous
#include <cuda_runtime.h>
#include <cuda_fp16.h>
#include <cstdint>

// ---------------- problem constants ----------------
#define K_DIM   256
#define N_DIM   256
#define M_CTA   64
#define N_CTA   128
#define THREADS 128           // 4 warps: 2 (M) x 2 (N), warp tile 32x64

// smem layout (bytes) -- unpadded, XOR-swizzled fp16 tiles (512 B rows)
#define OFF_SCALE 0                           // 128 f32
#define OFF_BIAS  512                         // 128 f32
#define OFF_A     1024
#define A_BYTES   (64 * 512)                  // 32768
#define OFF_B     (OFF_A + A_BYTES)           // 33792
#define B_BYTES   (128 * 512)                 // 65536
#define SMEM_TOTAL (OFF_B + B_BYTES)          // 99328 -> 2 CTAs/SM

__device__ __forceinline__ uint32_t smem_u32(const void* p) {
    uint32_t a;
    asm("{ .reg .u64 t; cvta.to.shared.u64 t, %1; cvt.u32.u64 %0, t; }"
        : "=r"(a) : "l"(p));
    return a;
}
__device__ __forceinline__ void cp16(uint32_t dst, const void* src) {
    asm volatile("cp.async.cg.shared.global [%0], [%1], 16;" :: "r"(dst), "l"(src) : "memory");
}
#define CP_COMMIT() asm volatile("cp.async.commit_group;" ::: "memory")
#define CP_WAIT0()  asm volatile("cp.async.wait_group 0;" ::: "memory")

__device__ __forceinline__ void ldsm4(uint32_t& r0, uint32_t& r1, uint32_t& r2, uint32_t& r3,
                                      uint32_t addr) {
    asm volatile("ldmatrix.sync.aligned.m8n8.x4.shared.b16 {%0,%1,%2,%3}, [%4];"
                 : "=r"(r0), "=r"(r1), "=r"(r2), "=r"(r3) : "r"(addr));
}
__device__ __forceinline__ void mma16816(float* c, const uint32_t* a, uint32_t b0, uint32_t b1) {
    asm volatile(
        "mma.sync.aligned.m16n8k16.row.col.f32.f16.f16.f32 "
        "{%0,%1,%2,%3}, {%4,%5,%6,%7}, {%8,%9}, {%0,%1,%2,%3};"
        : "+f"(c[0]), "+f"(c[1]), "+f"(c[2]), "+f"(c[3])
        : "r"(a[0]), "r"(a[1]), "r"(a[2]), "r"(a[3]), "r"(b0), "r"(b1));
}

// Binarized weight sign(W) as fp16 (+-1 exact), prepared per launch.
__device__ __align__(16) __half g_bsign[N_DIM * K_DIM];

__global__ void prep_bsign(const float* __restrict__ W) {
    int i = blockIdx.x * blockDim.x + threadIdx.x;
    if (i < N_DIM * K_DIM) {
        float w = W[i];
        g_bsign[i] = __float2half((w > 0.f) ? 1.f : ((w < 0.f) ? -1.f : 0.f));
    }
}

__global__ __launch_bounds__(THREADS, 2)
void binlin_gemm(const float* __restrict__ x,
                 const float* __restrict__ scale,
                 const float* __restrict__ bias,
                 float* __restrict__ out) {
    extern __shared__ char smem[];
    float* sScale = (float*)(smem + OFF_SCALE);
    float* sBias  = (float*)(smem + OFF_BIAS);
    __half* sA    = (__half*)(smem + OFF_A);
    const uint32_t sAu = smem_u32(smem + OFF_A);
    const uint32_t sBu = smem_u32(smem + OFF_B);

    const int tid  = threadIdx.x;
    const int wid  = tid >> 5;
    const int lane = tid & 31;
    const int wm   = wid & 1;        // 0..1 (M, 32 rows each)
    const int wn   = wid >> 1;       // 0..1 (N, 64 cols each)
    const int g    = lane >> 2;      // 0..7
    const int t    = lane & 3;       // 0..3

    const int mblk = blockIdx.x >> 1;
    const int nblk = blockIdx.x & 1;
    const int m_base = mblk * M_CTA;
    const int n_base = nblk * N_CTA;

    // ---- scale/bias for this N block ----
    sScale[tid] = scale[n_base + tid];
    sBias[tid]  = bias[n_base + tid];

    // ---- B tile via cp.async first (overlaps with A LDG below) ----
    {
        const __half* bsrc = g_bsign + (size_t)n_base * K_DIM;
        #pragma unroll
        for (int i = 0; i < 32; i++) {
            int c = tid + THREADS * i;          // 0..4095
            int r = c >> 5;
            int q = c & 31;
            cp16(sBu + r * 512 + 16 * (q ^ (r & 7)), bsrc + r * K_DIM + q * 8);
        }
    }
    CP_COMMIT();

    // ---- A tile: LDG fp32 -> cvt -> STS.128 fp16, swizzled ----
    const float* xbase = x + (size_t)m_base * K_DIM;
    #pragma unroll
    for (int i = 0; i < 16; i++) {
        int c  = tid + THREADS * i;             // 0..2047
        int r  = c >> 5;                        // row 0..63
        int cq = c & 31;                        // 16B dst chunk in row
        const float* src = xbase + (size_t)r * K_DIM + cq * 8;
        float4 v0 = *(const float4*)(src);
        float4 v1 = *(const float4*)(src + 4);
        __half2 h0 = __floats2half2_rn(v0.x, v0.y);
        __half2 h1 = __floats2half2_rn(v0.z, v0.w);
        __half2 h2 = __floats2half2_rn(v1.x, v1.y);
        __half2 h3 = __floats2half2_rn(v1.z, v1.w);
        uint4 u;
        u.x = *(uint32_t*)&h0; u.y = *(uint32_t*)&h1;
        u.z = *(uint32_t*)&h2; u.w = *(uint32_t*)&h3;
        *(uint4*)((char*)sA + r * 512 + 16 * (cq ^ (r & 7))) = u;
    }

    CP_WAIT0();
    __syncthreads();

    // ---- fragment addressing (swizzled, 512 B rows) ----
    const int arow = wm * 32 + (lane & 15);
    const int brow = wn * 64 + (lane & 15);
    const int kq   = lane >> 4;                 // 0/1

    float acc[2][8][4];
    #pragma unroll
    for (int i = 0; i < 2; i++)
        #pragma unroll
        for (int j = 0; j < 8; j++)
            #pragma unroll
            for (int e = 0; e < 4; e++)
                acc[i][j][e] = 0.f;

    uint32_t afr[3][2][4];     // [buf][mtile][4] -- triple buffer, prefetch dist 2
    uint32_t bfr[3][4][4];     // [buf][n16 group][4]

    auto loadFrags = [&](int bb, int ks) {
        const int q = 2 * ks + kq;
        #pragma unroll
        for (int i = 0; i < 2; i++) {
            const int r = arow + i * 16;
            ldsm4(afr[bb][i][0], afr[bb][i][1], afr[bb][i][2], afr[bb][i][3],
                  sAu + r * 512 + 16 * (q ^ (r & 7)));
        }
        #pragma unroll
        for (int p = 0; p < 4; p++) {
            const int r = brow + p * 16;
            ldsm4(bfr[bb][p][0], bfr[bb][p][1], bfr[bb][p][2], bfr[bb][p][3],
                  sBu + r * 512 + 16 * (q ^ (r & 7)));
        }
    };

    loadFrags(0, 0);
    loadFrags(1, 1);

    // ---- mainloop: 16 k-steps, no barriers, prefetch distance 2 ----
    #pragma unroll
    for (int ks = 0; ks < 16; ks++) {
        const int cur = ks % 3;
        if (ks < 14) loadFrags((ks + 2) % 3, ks + 2);
        #pragma unroll
        for (int i = 0; i < 2; i++)
            #pragma unroll
            for (int j = 0; j < 8; j++) {
                const int p = j >> 1, h = j & 1;
                mma16816(acc[i][j], afr[cur][i], bfr[cur][p][h], bfr[cur][p][h + 2]);
            }
    }

    // ---- register epilogue: scale*acc + bias, direct STG ----
    #pragma unroll
    for (int i = 0; i < 2; i++) {
        const int r0 = m_base + wm * 32 + i * 16 + g;
        float* dst0 = out + (size_t)r0 * N_DIM + n_base + wn * 64;
        float* dst1 = dst0 + 8 * N_DIM;
        #pragma unroll
        for (int j = 0; j < 8; j++) {
            const int col = j * 8 + 2 * t;
            const float2 sc = *(const float2*)(sScale + wn * 64 + col);
            const float2 bi = *(const float2*)(sBias  + wn * 64 + col);
            float2 v0, v1;
            v0.x = acc[i][j][0] * sc.x + bi.x;
            v0.y = acc[i][j][1] * sc.y + bi.y;
            v1.x = acc[i][j][2] * sc.x + bi.x;
            v1.y = acc[i][j][3] * sc.y + bi.y;
            *(float2*)(dst0 + col) = v0;
            *(float2*)(dst1 + col) = v1;
        }
    }
}

extern "C" void kernel_launch(void* const* d_in, const int* in_sizes, int n_in,
                              void* d_out, int out_size) {
    const float* x     = (const float*)d_in[0];
    const float* W     = (const float*)d_in[1];
    const float* scale = (const float*)d_in[2];
    const float* bias  = (const float*)d_in[3];
    float* out = (float*)d_out;

    const int M = in_sizes[0] / K_DIM;              // 131072
    const int grid = (M / M_CTA) * 2;               // 4096

    prep_bsign<<<(N_DIM * K_DIM + 255) / 256, 256>>>(W);

    cudaFuncSetAttribute(binlin_gemm, cudaFuncAttributeMaxDynamicSharedMemorySize, SMEM_TOTAL);
    binlin_gemm<<<grid, THREADS, SMEM_TOTAL>>>(x, scale, bias, out);
}

// round 13
// speedup vs baseline: 1.5268x; 1.2039x over previous
#include <cuda_runtime.h>
#include <cuda_fp16.h>
#include <cstdint>

// ---------------- problem constants ----------------
#define K_DIM   256
#define N_DIM   256
#define M_TILE  64
#define N_MTILES 2048          // 131072 / 64
#define THREADS 256            // 8 warps: 2(M) x 4(N), warp tile 32x64

// smem layout (bytes) -- unpadded XOR-swizzled fp16 tiles (512 B rows)
#define OFF_SCALE 0                            // 256 f32
#define OFF_BIAS  1024                         // 256 f32
#define OFF_A     2048
#define A_BYTES   (64 * 512)                   // 32768 per buffer, x2
#define OFF_B     (OFF_A + 2 * A_BYTES)        // 67584
#define B_BYTES   (256 * 512)                  // 131072
#define SMEM_TOTAL (OFF_B + B_BYTES)           // 198656 -> 1 CTA/SM, persistent

__device__ __forceinline__ uint32_t smem_u32(const void* p) {
    uint32_t a;
    asm("{ .reg .u64 t; cvta.to.shared.u64 t, %1; cvt.u32.u64 %0, t; }"
        : "=r"(a) : "l"(p));
    return a;
}
__device__ __forceinline__ void cp16(uint32_t dst, const void* src) {
    asm volatile("cp.async.cg.shared.global [%0], [%1], 16;" :: "r"(dst), "l"(src) : "memory");
}
#define CP_COMMIT() asm volatile("cp.async.commit_group;" ::: "memory")
#define CP_WAIT0()  asm volatile("cp.async.wait_group 0;" ::: "memory")

__device__ __forceinline__ void ldsm4(uint32_t& r0, uint32_t& r1, uint32_t& r2, uint32_t& r3,
                                      uint32_t addr) {
    asm volatile("ldmatrix.sync.aligned.m8n8.x4.shared.b16 {%0,%1,%2,%3}, [%4];"
                 : "=r"(r0), "=r"(r1), "=r"(r2), "=r"(r3) : "r"(addr));
}
__device__ __forceinline__ void mma16816(float* c, const uint32_t* a, uint32_t b0, uint32_t b1) {
    asm volatile(
        "mma.sync.aligned.m16n8k16.row.col.f32.f16.f16.f32 "
        "{%0,%1,%2,%3}, {%4,%5,%6,%7}, {%8,%9}, {%0,%1,%2,%3};"
        : "+f"(c[0]), "+f"(c[1]), "+f"(c[2]), "+f"(c[3])
        : "r"(a[0]), "r"(a[1]), "r"(a[2]), "r"(a[3]), "r"(b0), "r"(b1));
}
__device__ __forceinline__ void sts64(uint32_t addr, uint32_t u0, uint32_t u1) {
    asm volatile("st.shared.v2.u32 [%0], {%1,%2};" :: "r"(addr), "r"(u0), "r"(u1) : "memory");
}

// Binarized weight sign(W) as fp16 (+-1 exact), prepared per launch.
__device__ __align__(16) __half g_bsign[N_DIM * K_DIM];

__global__ void prep_bsign(const float* __restrict__ W) {
    int i = blockIdx.x * blockDim.x + threadIdx.x;
    if (i < N_DIM * K_DIM) {
        float w = W[i];
        g_bsign[i] = __float2half((w > 0.f) ? 1.f : ((w < 0.f) ? -1.f : 0.f));
    }
}

__global__ __launch_bounds__(THREADS, 1)
void binlin_gemm(const float* __restrict__ x,
                 const float* __restrict__ scale,
                 const float* __restrict__ bias,
                 float* __restrict__ out) {
    extern __shared__ char smem[];
    float* sScale = (float*)(smem + OFF_SCALE);
    float* sBias  = (float*)(smem + OFF_BIAS);
    const uint32_t sAu = smem_u32(smem + OFF_A);
    const uint32_t sBu = smem_u32(smem + OFF_B);

    const int tid  = threadIdx.x;
    const int wid  = tid >> 5;
    const int lane = tid & 31;
    const int wm   = wid & 1;        // 0..1 (M, 32 rows)
    const int wn   = wid >> 1;       // 0..3 (N, 64 cols)
    const int g    = lane >> 2;
    const int t    = lane & 3;

    const int stride = gridDim.x;

    // ---- scale/bias (full N) ----
    sScale[tid] = scale[tid];
    sBias[tid]  = bias[tid];

    // ---- B tile (full 256xK) via cp.async: 8192 x 16B, 32/thread ----
    #pragma unroll
    for (int i = 0; i < 32; i++) {
        int c = tid + THREADS * i;          // 0..8191
        int r = c >> 5;
        int q = c & 31;
        cp16(sBu + r * 512 + 16 * (q ^ (r & 7)), g_bsign + r * K_DIM + q * 8);
    }
    CP_COMMIT();

    // per-thread A item decomposition (item = tid + 256*i, i<16)
    // row = item>>6 (0..63), q = item&63 (float4 within row)
    float4 stg[16];

    auto ldgA = [&](int mt) {
        const float* src = x + (size_t)mt * M_TILE * K_DIM;
        #pragma unroll
        for (int i = 0; i < 16; i++) {
            int item = tid + THREADS * i;
            int r = item >> 6;
            int q = item & 63;
            stg[i] = __ldg((const float4*)(src + (size_t)r * K_DIM + q * 4));
        }
    };
    auto cvtsts = [&](int buf) {
        const uint32_t base = sAu + (uint32_t)buf * A_BYTES;
        #pragma unroll
        for (int i = 0; i < 16; i++) {
            int item = tid + THREADS * i;
            int r  = item >> 6;
            int q  = item & 63;
            __half2 h0 = __floats2half2_rn(stg[i].x, stg[i].y);
            __half2 h1 = __floats2half2_rn(stg[i].z, stg[i].w);
            uint32_t addr = base + r * 512 + 16 * ((q >> 1) ^ (r & 7)) + (q & 1) * 8;
            sts64(addr, *(uint32_t*)&h0, *(uint32_t*)&h1);
        }
    };

    // ---- first tile A into buf 0 ----
    int mt0 = blockIdx.x;
    ldgA(mt0);
    cvtsts(0);
    CP_WAIT0();
    __syncthreads();

    // ---- fragment addressing ----
    const int arow = wm * 32 + (lane & 15);
    const int brow = wn * 64 + (lane & 15);
    const int kq   = lane >> 4;

    uint32_t afr[2][2][4];
    uint32_t bfr[2][4][4];

    // ---- persistent tile loop ----
    int buf = 0;
    for (int mt = mt0; mt < N_MTILES; mt += stride, buf ^= 1) {
        const bool has_next = (mt + stride < N_MTILES);
        if (has_next) ldgA(mt + stride);      // drains under the mainloop

        const uint32_t abuf = sAu + (uint32_t)buf * A_BYTES;

        float acc[2][8][4];
        #pragma unroll
        for (int i = 0; i < 2; i++)
            #pragma unroll
            for (int j = 0; j < 8; j++)
                #pragma unroll
                for (int e = 0; e < 4; e++)
                    acc[i][j][e] = 0.f;

        auto loadFrags = [&](int bb, int ks) {
            const int q = 2 * ks + kq;
            #pragma unroll
            for (int i = 0; i < 2; i++) {
                const int r = arow + i * 16;
                ldsm4(afr[bb][i][0], afr[bb][i][1], afr[bb][i][2], afr[bb][i][3],
                      abuf + r * 512 + 16 * (q ^ (r & 7)));
            }
            #pragma unroll
            for (int p = 0; p < 4; p++) {
                const int r = brow + p * 16;
                ldsm4(bfr[bb][p][0], bfr[bb][p][1], bfr[bb][p][2], bfr[bb][p][3],
                      sBu + r * 512 + 16 * (q ^ (r & 7)));
            }
        };

        loadFrags(0, 0);
        #pragma unroll
        for (int ks = 0; ks < 16; ks++) {
            const int cur = ks & 1;
            if (ks < 15) loadFrags(cur ^ 1, ks + 1);
            #pragma unroll
            for (int i = 0; i < 2; i++)
                #pragma unroll
                for (int j = 0; j < 8; j++) {
                    const int p = j >> 1, h = j & 1;
                    mma16816(acc[i][j], afr[cur][i], bfr[cur][p][h], bfr[cur][p][h + 2]);
                }
        }

        // stage next tile's A into the other buffer (mainloop no longer reads it)
        if (has_next) cvtsts(buf ^ 1);

        // ---- epilogue: scale*acc + bias, direct STG ----
        const int m_base = mt * M_TILE;
        #pragma unroll
        for (int i = 0; i < 2; i++) {
            const int r0 = m_base + wm * 32 + i * 16 + g;
            float* dst0 = out + (size_t)r0 * N_DIM + wn * 64;
            float* dst1 = dst0 + 8 * N_DIM;
            #pragma unroll
            for (int j = 0; j < 8; j++) {
                const int col = j * 8 + 2 * t;
                const float2 sc = *(const float2*)(sScale + wn * 64 + col);
                const float2 bi = *(const float2*)(sBias  + wn * 64 + col);
                float2 v0, v1;
                v0.x = acc[i][j][0] * sc.x + bi.x;
                v0.y = acc[i][j][1] * sc.y + bi.y;
                v1.x = acc[i][j][2] * sc.x + bi.x;
                v1.y = acc[i][j][3] * sc.y + bi.y;
                *(float2*)(dst0 + col) = v0;
                *(float2*)(dst1 + col) = v1;
            }
        }

        __syncthreads();   // STS(buf^1) visible; buf reads done before next overwrite
    }
}

extern "C" void kernel_launch(void* const* d_in, const int* in_sizes, int n_in,
                              void* d_out, int out_size) {
    const float* x     = (const float*)d_in[0];
    const float* W     = (const float*)d_in[1];
    const float* scale = (const float*)d_in[2];
    const float* bias  = (const float*)d_in[3];
    float* out = (float*)d_out;

    int nsm = 148;
    cudaDeviceGetAttribute(&nsm, cudaDevAttrMultiProcessorCount, 0);
    if (nsm <= 0 || nsm > N_MTILES) nsm = 148;

    prep_bsign<<<(N_DIM * K_DIM + 255) / 256, 256>>>(W);

    cudaFuncSetAttribute(binlin_gemm, cudaFuncAttributeMaxDynamicSharedMemorySize, SMEM_TOTAL);
    binlin_gemm<<<nsm, THREADS, SMEM_TOTAL>>>(x, scale, bias, out);
}